// round 1
// baseline (speedup 1.0000x reference)
#include <cuda_runtime.h>
#include <cuda_bf16.h>

#define BB 4
#define SS 2048
#define EE 1024
#define HH 16
#define DD 64
#define BSROWS (BB * SS)   // 8192

// Scratch (device globals: allocation-free per harness rules).
__device__ float g_q[BSROWS * EE];
__device__ float g_k[BSROWS * EE];
__device__ float g_v[BSROWS * EE];
__device__ float g_attn[BSROWS * EE];

// ---------------------------------------------------------------------------
// GEMM: C[M,N] = A[M,K] * W[N,K]^T (+ bias[N])
// 128x128 block tile, BK=8, 256 threads, 8x8 per thread (split 4+4).
// ---------------------------------------------------------------------------
__global__ void __launch_bounds__(256, 2)
gemm_nt(const float* __restrict__ A, const float* __restrict__ W,
        const float* __restrict__ bias, float* __restrict__ C,
        int M, int N, int K)
{
    __shared__ float As[8][128];
    __shared__ float Bs[8][128];

    const int tid  = threadIdx.x;
    const int brow = blockIdx.y * 128;
    const int bcol = blockIdx.x * 128;

    const int lr = tid >> 1;         // 0..127 (row within tile for loads)
    const int lk = (tid & 1) * 4;    // 0 or 4 (k offset for float4 load)

    const int r0 = (tid >> 4) * 4;   // 0..60
    const int c0 = (tid & 15) * 4;   // 0..60

    float acc[8][8];
#pragma unroll
    for (int i = 0; i < 8; i++)
#pragma unroll
        for (int j = 0; j < 8; j++) acc[i][j] = 0.f;

    const float* Aptr = A + (long)(brow + lr) * K + lk;
    const float* Wptr = W + (long)(bcol + lr) * K + lk;

    for (int k0 = 0; k0 < K; k0 += 8) {
        float4 a = *(const float4*)(Aptr + k0);
        float4 b = *(const float4*)(Wptr + k0);
        As[lk + 0][lr] = a.x; As[lk + 1][lr] = a.y;
        As[lk + 2][lr] = a.z; As[lk + 3][lr] = a.w;
        Bs[lk + 0][lr] = b.x; Bs[lk + 1][lr] = b.y;
        Bs[lk + 2][lr] = b.z; Bs[lk + 3][lr] = b.w;
        __syncthreads();

#pragma unroll
        for (int kk = 0; kk < 8; kk++) {
            float4 a0 = *(const float4*)&As[kk][r0];
            float4 a1 = *(const float4*)&As[kk][r0 + 64];
            float4 b0 = *(const float4*)&Bs[kk][c0];
            float4 b1 = *(const float4*)&Bs[kk][c0 + 64];
            float ra[8] = {a0.x, a0.y, a0.z, a0.w, a1.x, a1.y, a1.z, a1.w};
            float rb[8] = {b0.x, b0.y, b0.z, b0.w, b1.x, b1.y, b1.z, b1.w};
#pragma unroll
            for (int i = 0; i < 8; i++)
#pragma unroll
                for (int j = 0; j < 8; j++)
                    acc[i][j] = fmaf(ra[i], rb[j], acc[i][j]);
        }
        __syncthreads();
    }

    float4 bv0 = make_float4(0.f, 0.f, 0.f, 0.f);
    float4 bv1 = make_float4(0.f, 0.f, 0.f, 0.f);
    if (bias) {
        bv0 = *(const float4*)(bias + bcol + c0);
        bv1 = *(const float4*)(bias + bcol + c0 + 64);
    }

#pragma unroll
    for (int i = 0; i < 8; i++) {
        int row = brow + r0 + ((i < 4) ? i : (60 + i));   // i>=4 -> r0+64+(i-4)
        float4 v0 = make_float4(acc[i][0] + bv0.x, acc[i][1] + bv0.y,
                                acc[i][2] + bv0.z, acc[i][3] + bv0.w);
        float4 v1 = make_float4(acc[i][4] + bv1.x, acc[i][5] + bv1.y,
                                acc[i][6] + bv1.z, acc[i][7] + bv1.w);
        *(float4*)(C + (long)row * N + bcol + c0)      = v0;
        *(float4*)(C + (long)row * N + bcol + c0 + 64) = v1;
    }
}

// ---------------------------------------------------------------------------
// Flash attention: causal, scale = 1/sqrt(E) = 1/32.
// Q,K,V,O all in [B,S,E] layout; head h uses columns [h*64, h*64+64).
// 64x64 tiles, 256 threads, 4x4 micro-tile per thread.
// ---------------------------------------------------------------------------
#define FP 68      // padded shared stride (float4-aligned, bank-spread)
#define NEG_BIG (-1e30f)

__global__ void __launch_bounds__(256)
flash_kernel(const float* __restrict__ Qg, const float* __restrict__ Kg,
             const float* __restrict__ Vg, float* __restrict__ Og)
{
    extern __shared__ float smem[];
    float* Qs = smem;                 // [d][r], 64 x FP  (transposed)
    float* Ks = smem + 64 * FP;       // [d][c], transposed
    float* Vs = smem + 2 * 64 * FP;   // [kv][c], row-major
    float* Ps = smem + 3 * 64 * FP;   // [r][kv], row-major

    const int tid = threadIdx.x;
    const int qt  = blockIdx.x;                 // q tile (0..31)
    const int b   = blockIdx.y / HH;
    const int h   = blockIdx.y % HH;

    const float* Qb = Qg + (long)b * SS * EE + h * DD;
    const float* Kb = Kg + (long)b * SS * EE + h * DD;
    const float* Vb = Vg + (long)b * SS * EE + h * DD;
    float*       Ob = Og + (long)b * SS * EE + h * DD;

    const int r0  = (tid >> 4) * 4;
    const int c0  = (tid & 15) * 4;
    const int lr  = tid >> 4;     // 0..15 (load row group)
    const int lc4 = tid & 15;     // float4 column index

    // Load Q tile transposed: Qs[d][r]
#pragma unroll
    for (int it = 0; it < 4; it++) {
        int r = lr + it * 16;
        float4 v = *(const float4*)(Qb + (long)(qt * 64 + r) * EE + lc4 * 4);
        Qs[(lc4 * 4 + 0) * FP + r] = v.x;
        Qs[(lc4 * 4 + 1) * FP + r] = v.y;
        Qs[(lc4 * 4 + 2) * FP + r] = v.z;
        Qs[(lc4 * 4 + 3) * FP + r] = v.w;
    }

    float m_i[4], l_i[4], o[4][4];
#pragma unroll
    for (int i = 0; i < 4; i++) {
        m_i[i] = NEG_BIG; l_i[i] = 0.f;
#pragma unroll
        for (int j = 0; j < 4; j++) o[i][j] = 0.f;
    }

    const float scale = 0.03125f;   // 1/sqrt(1024)

    for (int kt = 0; kt <= qt; kt++) {
        // Load K (transposed) and V (row-major)
#pragma unroll
        for (int it = 0; it < 4; it++) {
            int r = lr + it * 16;
            float4 kv4 = *(const float4*)(Kb + (long)(kt * 64 + r) * EE + lc4 * 4);
            Ks[(lc4 * 4 + 0) * FP + r] = kv4.x;
            Ks[(lc4 * 4 + 1) * FP + r] = kv4.y;
            Ks[(lc4 * 4 + 2) * FP + r] = kv4.z;
            Ks[(lc4 * 4 + 3) * FP + r] = kv4.w;
            float4 vv = *(const float4*)(Vb + (long)(kt * 64 + r) * EE + lc4 * 4);
            *(float4*)&Vs[r * FP + lc4 * 4] = vv;
        }
        __syncthreads();

        // S = Q K^T (4x4 per thread)
        float s[4][4];
#pragma unroll
        for (int i = 0; i < 4; i++)
#pragma unroll
            for (int j = 0; j < 4; j++) s[i][j] = 0.f;

#pragma unroll 8
        for (int d = 0; d < 64; d++) {
            float4 qa = *(const float4*)&Qs[d * FP + r0];
            float4 kb = *(const float4*)&Ks[d * FP + c0];
            float ra[4] = {qa.x, qa.y, qa.z, qa.w};
            float rb[4] = {kb.x, kb.y, kb.z, kb.w};
#pragma unroll
            for (int i = 0; i < 4; i++)
#pragma unroll
                for (int j = 0; j < 4; j++)
                    s[i][j] = fmaf(ra[i], rb[j], s[i][j]);
        }

        // scale + causal mask
        if (kt == qt) {
#pragma unroll
            for (int i = 0; i < 4; i++)
#pragma unroll
                for (int j = 0; j < 4; j++)
                    s[i][j] = (c0 + j > r0 + i) ? NEG_BIG : s[i][j] * scale;
        } else {
#pragma unroll
            for (int i = 0; i < 4; i++)
#pragma unroll
                for (int j = 0; j < 4; j++) s[i][j] *= scale;
        }

        // row max across tile (reduce over 16 tx lanes)
        float rmax[4];
#pragma unroll
        for (int i = 0; i < 4; i++) {
            rmax[i] = fmaxf(fmaxf(s[i][0], s[i][1]), fmaxf(s[i][2], s[i][3]));
#pragma unroll
            for (int ofs = 1; ofs < 16; ofs <<= 1)
                rmax[i] = fmaxf(rmax[i], __shfl_xor_sync(0xffffffffu, rmax[i], ofs));
        }

        float cf[4], rsum[4];
#pragma unroll
        for (int i = 0; i < 4; i++) {
            float mnew = fmaxf(m_i[i], rmax[i]);
            cf[i] = __expf(m_i[i] - mnew);
            m_i[i] = mnew;
            rsum[i] = 0.f;
#pragma unroll
            for (int j = 0; j < 4; j++) {
                float p = __expf(s[i][j] - mnew);
                Ps[(r0 + i) * FP + c0 + j] = p;
                rsum[i] += p;
            }
        }
#pragma unroll
        for (int i = 0; i < 4; i++) {
#pragma unroll
            for (int ofs = 1; ofs < 16; ofs <<= 1)
                rsum[i] += __shfl_xor_sync(0xffffffffu, rsum[i], ofs);
            l_i[i] = l_i[i] * cf[i] + rsum[i];
#pragma unroll
            for (int j = 0; j < 4; j++) o[i][j] *= cf[i];
        }
        __syncthreads();   // Ps visible to all

        // O += P V
#pragma unroll 8
        for (int kv = 0; kv < 64; kv++) {
            float4 vb = *(const float4*)&Vs[kv * FP + c0];
            float rvb[4] = {vb.x, vb.y, vb.z, vb.w};
            float pa[4];
#pragma unroll
            for (int i = 0; i < 4; i++) pa[i] = Ps[(r0 + i) * FP + kv];
#pragma unroll
            for (int i = 0; i < 4; i++)
#pragma unroll
                for (int j = 0; j < 4; j++)
                    o[i][j] = fmaf(pa[i], rvb[j], o[i][j]);
        }
        __syncthreads();   // protect Ks/Vs/Ps before next tile
    }

    // epilogue: O / l
#pragma unroll
    for (int i = 0; i < 4; i++) {
        float inv = 1.f / l_i[i];
        float4 v = make_float4(o[i][0] * inv, o[i][1] * inv,
                               o[i][2] * inv, o[i][3] * inv);
        *(float4*)(Ob + (long)(qt * 64 + r0 + i) * EE + c0) = v;
    }
}

// ---------------------------------------------------------------------------
extern "C" void kernel_launch(void* const* d_in, const int* in_sizes, int n_in,
                              void* d_out, int out_size)
{
    const float* x  = (const float*)d_in[0];
    const float* Wq = (const float*)d_in[1];
    const float* Wk = (const float*)d_in[2];
    const float* Wv = (const float*)d_in[3];
    const float* Wo = (const float*)d_in[4];
    const float* bo = (const float*)d_in[5];
    float* out = (float*)d_out;

    float *q, *k, *v, *a;
    cudaGetSymbolAddress((void**)&q, g_q);
    cudaGetSymbolAddress((void**)&k, g_k);
    cudaGetSymbolAddress((void**)&v, g_v);
    cudaGetSymbolAddress((void**)&a, g_attn);

    dim3 gg(EE / 128, BSROWS / 128);   // (8, 64)
    gemm_nt<<<gg, 256>>>(x, Wq, nullptr, q, BSROWS, EE, EE);
    gemm_nt<<<gg, 256>>>(x, Wk, nullptr, k, BSROWS, EE, EE);
    gemm_nt<<<gg, 256>>>(x, Wv, nullptr, v, BSROWS, EE, EE);

    const int smem_bytes = 4 * 64 * FP * sizeof(float);  // ~69.6 KB
    cudaFuncSetAttribute(flash_kernel,
                         cudaFuncAttributeMaxDynamicSharedMemorySize, smem_bytes);
    flash_kernel<<<dim3(SS / 64, BB * HH), 256, smem_bytes>>>(q, k, v, a);

    gemm_nt<<<gg, 256>>>(a, Wo, bo, out, BSROWS, EE, EE);
}

// round 5
// speedup vs baseline: 1.5008x; 1.5008x over previous
#include <cuda_runtime.h>
#include <cuda_bf16.h>
#include <cstdint>

#define BB 4
#define SS 2048
#define EE 1024
#define HH 16
#define DD 64
#define BSROWS (BB * SS)   // 8192

// Scratch (device globals: allocation-free per harness rules).
__device__ float g_q[BSROWS * EE];
__device__ float g_k[BSROWS * EE];
__device__ float g_v[BSROWS * EE];
__device__ float g_attn[BSROWS * EE];

// ---------------------------------------------------------------------------
// helpers
// ---------------------------------------------------------------------------
__device__ __forceinline__ uint32_t smem_u32(const void* p) {
    uint32_t a;
    asm("{ .reg .u64 t; cvta.to.shared.u64 t, %1; cvt.u32.u64 %0, t; }" : "=r"(a) : "l"(p));
    return a;
}
__device__ __forceinline__ uint32_t f2tf32(float f) {
    uint32_t r;
    asm("cvt.rna.tf32.f32 %0, %1;" : "=r"(r) : "f"(f));
    return r;
}
__device__ __forceinline__ void cp_async16(uint32_t dst, const void* src) {
    asm volatile("cp.async.ca.shared.global [%0], [%1], 16;" :: "r"(dst), "l"(src));
}
#define CP_COMMIT() asm volatile("cp.async.commit_group;" ::: "memory")
#define CP_WAIT(n)  asm volatile("cp.async.wait_group %0;" :: "n"(n) : "memory")

__device__ __forceinline__ void mma_tf32(float* c, const uint32_t* a, const uint32_t* b) {
    asm volatile(
        "mma.sync.aligned.m16n8k8.row.col.f32.tf32.tf32.f32 "
        "{%0,%1,%2,%3}, {%4,%5,%6,%7}, {%8,%9}, {%0,%1,%2,%3};"
        : "+f"(c[0]), "+f"(c[1]), "+f"(c[2]), "+f"(c[3])
        : "r"(a[0]), "r"(a[1]), "r"(a[2]), "r"(a[3]), "r"(b[0]), "r"(b[1]));
}

// ---------------------------------------------------------------------------
// tf32 mma.sync GEMM: C[M,N] = A[M,K] * W[N,K]^T (+bias). M=8192, N=K=1024.
// CTA 128x128, BK=32, 8 warps (2x4), warp tile 64x32, double-buffered cp.async.
// ---------------------------------------------------------------------------
#define BK 32
#define SSTR 36                      // smem row stride (floats)
#define TILE_F (128 * SSTR)          // floats per matrix per stage (4608)
#define NCHUNK (EE / BK)             // 32

static_assert(BSROWS % 128 == 0 && EE % 128 == 0 && EE % BK == 0, "tile geometry");

__global__ void __launch_bounds__(256)
gemm_tf32(const float* __restrict__ A, const float* __restrict__ W,
          const float* __restrict__ bias, float* __restrict__ C)
{
    extern __shared__ float sm[];
    // layout: [buf][mat] : buf0 A @0, buf0 W @TILE_F, buf1 A @2*TILE_F, buf1 W @3*TILE_F
    const uint32_t smb = smem_u32(sm);

    const int t    = threadIdx.x;
    const int brow = blockIdx.y * 128;
    const int bcol = blockIdx.x * 128;

    const int lane = t & 31;
    const int w    = t >> 5;
    const int wm   = (w & 1) * 64;        // warp row offset
    const int wn   = (w >> 1) * 32;       // warp col offset
    const int g    = lane >> 2;           // groupID 0..7
    const int tg   = lane & 3;            // thread-in-group 0..3

    // staging assignment: 128 rows x 8 float4; thread t -> row t>>1, 4 float4s
    const int sr = t >> 1;
    const int sc = (t & 1) * 16;          // float offset (0 or 16)
    const float* Ag = A + (long)(brow + sr) * EE + sc;
    const float* Wg = W + (long)(bcol + sr) * EE + sc;
    const uint32_t sdA = smb + (sr * SSTR + sc) * 4;
    const uint32_t sdW = sdA + TILE_F * 4;

    float acc[4][4][4];
#pragma unroll
    for (int i = 0; i < 4; i++)
#pragma unroll
        for (int j = 0; j < 4; j++)
#pragma unroll
            for (int r = 0; r < 4; r++) acc[i][j][r] = 0.f;

    // prologue: stage chunk 0 into buffer 0
#pragma unroll
    for (int j = 0; j < 4; j++) {
        cp_async16(sdA + j * 16, Ag + j * 4);
        cp_async16(sdW + j * 16, Wg + j * 4);
    }
    CP_COMMIT();

    for (int kc = 0; kc < NCHUNK; kc++) {
        const int cur = kc & 1, nxt = cur ^ 1;

        if (kc + 1 < NCHUNK) {
            const int k0 = (kc + 1) * BK;
            const uint32_t bofs = nxt * 2 * TILE_F * 4;
#pragma unroll
            for (int j = 0; j < 4; j++) {
                cp_async16(sdA + bofs + j * 16, Ag + k0 + j * 4);
                cp_async16(sdW + bofs + j * 16, Wg + k0 + j * 4);
            }
            CP_COMMIT();
            CP_WAIT(1);
        } else {
            CP_WAIT(0);
        }
        __syncthreads();

        const float* As = sm + cur * 2 * TILE_F;
        const float* Ws = As + TILE_F;
        const int pa = (wm + g) * SSTR + tg;
        const int pb = (wn + g) * SSTR + tg;

#pragma unroll
        for (int kk = 0; kk < 4; kk++) {
            uint32_t af[4][4], bf[4][2];
#pragma unroll
            for (int mt = 0; mt < 4; mt++) {
                const int ib = pa + mt * 16 * SSTR + kk * 8;
                af[mt][0] = f2tf32(As[ib]);
                af[mt][1] = f2tf32(As[ib + 8 * SSTR]);
                af[mt][2] = f2tf32(As[ib + 4]);
                af[mt][3] = f2tf32(As[ib + 8 * SSTR + 4]);
            }
#pragma unroll
            for (int nt = 0; nt < 4; nt++) {
                const int ib = pb + nt * 8 * SSTR + kk * 8;
                bf[nt][0] = f2tf32(Ws[ib]);
                bf[nt][1] = f2tf32(Ws[ib + 4]);
            }
#pragma unroll
            for (int mt = 0; mt < 4; mt++)
#pragma unroll
                for (int nt = 0; nt < 4; nt++)
                    mma_tf32(acc[mt][nt], af[mt], bf[nt]);
        }
        __syncthreads();
    }

    // epilogue
#pragma unroll
    for (int mt = 0; mt < 4; mt++) {
#pragma unroll
        for (int nt = 0; nt < 4; nt++) {
            const int row = brow + wm + mt * 16 + g;
            const int col = bcol + wn + nt * 8 + 2 * tg;
            float b0 = 0.f, b1 = 0.f;
            if (bias) { b0 = bias[col]; b1 = bias[col + 1]; }
            *(float2*)(C + (long)row * EE + col) =
                make_float2(acc[mt][nt][0] + b0, acc[mt][nt][1] + b1);
            *(float2*)(C + (long)(row + 8) * EE + col) =
                make_float2(acc[mt][nt][2] + b0, acc[mt][nt][3] + b1);
        }
    }
}

// ---------------------------------------------------------------------------
// Flash attention: causal, scale = 1/sqrt(E) = 1/32. (unchanged from R1)
// ---------------------------------------------------------------------------
#define FP 68
#define NEG_BIG (-1e30f)

__global__ void __launch_bounds__(256)
flash_kernel(const float* __restrict__ Qg, const float* __restrict__ Kg,
             const float* __restrict__ Vg, float* __restrict__ Og)
{
    extern __shared__ float smem[];
    float* Qs = smem;
    float* Ks = smem + 64 * FP;
    float* Vs = smem + 2 * 64 * FP;
    float* Ps = smem + 3 * 64 * FP;

    const int tid = threadIdx.x;
    const int qt  = blockIdx.x;
    const int b   = blockIdx.y / HH;
    const int h   = blockIdx.y % HH;

    const float* Qb = Qg + (long)b * SS * EE + h * DD;
    const float* Kb = Kg + (long)b * SS * EE + h * DD;
    const float* Vb = Vg + (long)b * SS * EE + h * DD;
    float*       Ob = Og + (long)b * SS * EE + h * DD;

    const int r0  = (tid >> 4) * 4;
    const int c0  = (tid & 15) * 4;
    const int lr  = tid >> 4;
    const int lc4 = tid & 15;

#pragma unroll
    for (int it = 0; it < 4; it++) {
        int r = lr + it * 16;
        float4 v = *(const float4*)(Qb + (long)(qt * 64 + r) * EE + lc4 * 4);
        Qs[(lc4 * 4 + 0) * FP + r] = v.x;
        Qs[(lc4 * 4 + 1) * FP + r] = v.y;
        Qs[(lc4 * 4 + 2) * FP + r] = v.z;
        Qs[(lc4 * 4 + 3) * FP + r] = v.w;
    }

    float m_i[4], l_i[4], o[4][4];
#pragma unroll
    for (int i = 0; i < 4; i++) {
        m_i[i] = NEG_BIG; l_i[i] = 0.f;
#pragma unroll
        for (int j = 0; j < 4; j++) o[i][j] = 0.f;
    }

    const float scale = 0.03125f;

    for (int kt = 0; kt <= qt; kt++) {
#pragma unroll
        for (int it = 0; it < 4; it++) {
            int r = lr + it * 16;
            float4 kv4 = *(const float4*)(Kb + (long)(kt * 64 + r) * EE + lc4 * 4);
            Ks[(lc4 * 4 + 0) * FP + r] = kv4.x;
            Ks[(lc4 * 4 + 1) * FP + r] = kv4.y;
            Ks[(lc4 * 4 + 2) * FP + r] = kv4.z;
            Ks[(lc4 * 4 + 3) * FP + r] = kv4.w;
            float4 vv = *(const float4*)(Vb + (long)(kt * 64 + r) * EE + lc4 * 4);
            *(float4*)&Vs[r * FP + lc4 * 4] = vv;
        }
        __syncthreads();

        float s[4][4];
#pragma unroll
        for (int i = 0; i < 4; i++)
#pragma unroll
            for (int j = 0; j < 4; j++) s[i][j] = 0.f;

#pragma unroll 8
        for (int d = 0; d < 64; d++) {
            float4 qa = *(const float4*)&Qs[d * FP + r0];
            float4 kb = *(const float4*)&Ks[d * FP + c0];
            float ra[4] = {qa.x, qa.y, qa.z, qa.w};
            float rb[4] = {kb.x, kb.y, kb.z, kb.w};
#pragma unroll
            for (int i = 0; i < 4; i++)
#pragma unroll
                for (int j = 0; j < 4; j++)
                    s[i][j] = fmaf(ra[i], rb[j], s[i][j]);
        }

        if (kt == qt) {
#pragma unroll
            for (int i = 0; i < 4; i++)
#pragma unroll
                for (int j = 0; j < 4; j++)
                    s[i][j] = (c0 + j > r0 + i) ? NEG_BIG : s[i][j] * scale;
        } else {
#pragma unroll
            for (int i = 0; i < 4; i++)
#pragma unroll
                for (int j = 0; j < 4; j++) s[i][j] *= scale;
        }

        float rmax[4];
#pragma unroll
        for (int i = 0; i < 4; i++) {
            rmax[i] = fmaxf(fmaxf(s[i][0], s[i][1]), fmaxf(s[i][2], s[i][3]));
#pragma unroll
            for (int ofs = 1; ofs < 16; ofs <<= 1)
                rmax[i] = fmaxf(rmax[i], __shfl_xor_sync(0xffffffffu, rmax[i], ofs));
        }

        float cf[4], rsum[4];
#pragma unroll
        for (int i = 0; i < 4; i++) {
            float mnew = fmaxf(m_i[i], rmax[i]);
            cf[i] = __expf(m_i[i] - mnew);
            m_i[i] = mnew;
            rsum[i] = 0.f;
#pragma unroll
            for (int j = 0; j < 4; j++) {
                float p = __expf(s[i][j] - mnew);
                Ps[(r0 + i) * FP + c0 + j] = p;
                rsum[i] += p;
            }
        }
#pragma unroll
        for (int i = 0; i < 4; i++) {
#pragma unroll
            for (int ofs = 1; ofs < 16; ofs <<= 1)
                rsum[i] += __shfl_xor_sync(0xffffffffu, rsum[i], ofs);
            l_i[i] = l_i[i] * cf[i] + rsum[i];
#pragma unroll
            for (int j = 0; j < 4; j++) o[i][j] *= cf[i];
        }
        __syncthreads();

#pragma unroll 8
        for (int kv = 0; kv < 64; kv++) {
            float4 vb = *(const float4*)&Vs[kv * FP + c0];
            float rvb[4] = {vb.x, vb.y, vb.z, vb.w};
            float pa[4];
#pragma unroll
            for (int i = 0; i < 4; i++) pa[i] = Ps[(r0 + i) * FP + kv];
#pragma unroll
            for (int i = 0; i < 4; i++)
#pragma unroll
                for (int j = 0; j < 4; j++)
                    o[i][j] = fmaf(pa[i], rvb[j], o[i][j]);
        }
        __syncthreads();
    }

#pragma unroll
    for (int i = 0; i < 4; i++) {
        float inv = 1.f / l_i[i];
        float4 v = make_float4(o[i][0] * inv, o[i][1] * inv,
                               o[i][2] * inv, o[i][3] * inv);
        *(float4*)(Ob + (long)(qt * 64 + r0 + i) * EE + c0) = v;
    }
}

// ---------------------------------------------------------------------------
extern "C" void kernel_launch(void* const* d_in, const int* in_sizes, int n_in,
                              void* d_out, int out_size)
{
    const float* x  = (const float*)d_in[0];
    const float* Wq = (const float*)d_in[1];
    const float* Wk = (const float*)d_in[2];
    const float* Wv = (const float*)d_in[3];
    const float* Wo = (const float*)d_in[4];
    const float* bo = (const float*)d_in[5];
    float* out = (float*)d_out;

    float *q, *k, *v, *a;
    cudaGetSymbolAddress((void**)&q, g_q);
    cudaGetSymbolAddress((void**)&k, g_k);
    cudaGetSymbolAddress((void**)&v, g_v);
    cudaGetSymbolAddress((void**)&a, g_attn);

    const int gemm_smem = 4 * TILE_F * sizeof(float);   // 73728 B
    cudaFuncSetAttribute(gemm_tf32,
                         cudaFuncAttributeMaxDynamicSharedMemorySize, gemm_smem);

    dim3 gg(EE / 128, BSROWS / 128);   // (8, 64)
    gemm_tf32<<<gg, 256, gemm_smem>>>(x, Wq, nullptr, q);
    gemm_tf32<<<gg, 256, gemm_smem>>>(x, Wk, nullptr, k);
    gemm_tf32<<<gg, 256, gemm_smem>>>(x, Wv, nullptr, v);

    const int smem_bytes = 4 * 64 * FP * sizeof(float);
    cudaFuncSetAttribute(flash_kernel,
                         cudaFuncAttributeMaxDynamicSharedMemorySize, smem_bytes);
    flash_kernel<<<dim3(SS / 64, BB * HH), 256, smem_bytes>>>(q, k, v, a);

    gemm_tf32<<<gg, 256, gemm_smem>>>(a, Wo, bo, out);
}

// round 6
// speedup vs baseline: 2.3711x; 1.5799x over previous
#include <cuda_runtime.h>
#include <cuda_bf16.h>
#include <cstdint>

#define BB 4
#define SS 2048
#define EE 1024
#define HH 16
#define DD 64
#define BSROWS (BB * SS)   // 8192

// Scratch (device globals: allocation-free per harness rules).
__device__ float g_q[BSROWS * EE];
__device__ float g_k[BSROWS * EE];
__device__ float g_v[BSROWS * EE];
__device__ float g_attn[BSROWS * EE];

// ---------------------------------------------------------------------------
// helpers
// ---------------------------------------------------------------------------
__device__ __forceinline__ uint32_t smem_u32(const void* p) {
    uint32_t a;
    asm("{ .reg .u64 t; cvta.to.shared.u64 t, %1; cvt.u32.u64 %0, t; }" : "=r"(a) : "l"(p));
    return a;
}
__device__ __forceinline__ uint32_t f2tf32(float f) {
    uint32_t r;
    asm("cvt.rna.tf32.f32 %0, %1;" : "=r"(r) : "f"(f));
    return r;
}
__device__ __forceinline__ void cp_async16(uint32_t dst, const void* src) {
    asm volatile("cp.async.ca.shared.global [%0], [%1], 16;" :: "r"(dst), "l"(src));
}
#define CP_COMMIT() asm volatile("cp.async.commit_group;" ::: "memory")
#define CP_WAIT(n)  asm volatile("cp.async.wait_group %0;" :: "n"(n) : "memory")

__device__ __forceinline__ void mma_tf32(float* c, const uint32_t* a, const uint32_t* b) {
    asm volatile(
        "mma.sync.aligned.m16n8k8.row.col.f32.tf32.tf32.f32 "
        "{%0,%1,%2,%3}, {%4,%5,%6,%7}, {%8,%9}, {%0,%1,%2,%3};"
        : "+f"(c[0]), "+f"(c[1]), "+f"(c[2]), "+f"(c[3])
        : "r"(a[0]), "r"(a[1]), "r"(a[2]), "r"(a[3]), "r"(b[0]), "r"(b[1]));
}

// ---------------------------------------------------------------------------
// tf32 mma.sync GEMM (unchanged from R5, passing @ ~198us each)
// ---------------------------------------------------------------------------
#define BK 32
#define SSTR 36
#define TILE_F (128 * SSTR)
#define NCHUNK (EE / BK)

__global__ void __launch_bounds__(256)
gemm_tf32(const float* __restrict__ A, const float* __restrict__ W,
          const float* __restrict__ bias, float* __restrict__ C)
{
    extern __shared__ float sm[];
    const uint32_t smb = smem_u32(sm);

    const int t    = threadIdx.x;
    const int brow = blockIdx.y * 128;
    const int bcol = blockIdx.x * 128;

    const int lane = t & 31;
    const int w    = t >> 5;
    const int wm   = (w & 1) * 64;
    const int wn   = (w >> 1) * 32;
    const int g    = lane >> 2;
    const int tg   = lane & 3;

    const int sr = t >> 1;
    const int sc = (t & 1) * 16;
    const float* Ag = A + (long)(brow + sr) * EE + sc;
    const float* Wg = W + (long)(bcol + sr) * EE + sc;
    const uint32_t sdA = smb + (sr * SSTR + sc) * 4;
    const uint32_t sdW = sdA + TILE_F * 4;

    float acc[4][4][4];
#pragma unroll
    for (int i = 0; i < 4; i++)
#pragma unroll
        for (int j = 0; j < 4; j++)
#pragma unroll
            for (int r = 0; r < 4; r++) acc[i][j][r] = 0.f;

#pragma unroll
    for (int j = 0; j < 4; j++) {
        cp_async16(sdA + j * 16, Ag + j * 4);
        cp_async16(sdW + j * 16, Wg + j * 4);
    }
    CP_COMMIT();

    for (int kc = 0; kc < NCHUNK; kc++) {
        const int cur = kc & 1, nxt = cur ^ 1;

        if (kc + 1 < NCHUNK) {
            const int k0 = (kc + 1) * BK;
            const uint32_t bofs = nxt * 2 * TILE_F * 4;
#pragma unroll
            for (int j = 0; j < 4; j++) {
                cp_async16(sdA + bofs + j * 16, Ag + k0 + j * 4);
                cp_async16(sdW + bofs + j * 16, Wg + k0 + j * 4);
            }
            CP_COMMIT();
            CP_WAIT(1);
        } else {
            CP_WAIT(0);
        }
        __syncthreads();

        const float* As = sm + cur * 2 * TILE_F;
        const float* Ws = As + TILE_F;
        const int pa = (wm + g) * SSTR + tg;
        const int pb = (wn + g) * SSTR + tg;

#pragma unroll
        for (int kk = 0; kk < 4; kk++) {
            uint32_t af[4][4], bf[4][2];
#pragma unroll
            for (int mt = 0; mt < 4; mt++) {
                const int ib = pa + mt * 16 * SSTR + kk * 8;
                af[mt][0] = f2tf32(As[ib]);
                af[mt][1] = f2tf32(As[ib + 8 * SSTR]);
                af[mt][2] = f2tf32(As[ib + 4]);
                af[mt][3] = f2tf32(As[ib + 8 * SSTR + 4]);
            }
#pragma unroll
            for (int nt = 0; nt < 4; nt++) {
                const int ib = pb + nt * 8 * SSTR + kk * 8;
                bf[nt][0] = f2tf32(Ws[ib]);
                bf[nt][1] = f2tf32(Ws[ib + 4]);
            }
#pragma unroll
            for (int mt = 0; mt < 4; mt++)
#pragma unroll
                for (int nt = 0; nt < 4; nt++)
                    mma_tf32(acc[mt][nt], af[mt], bf[nt]);
        }
        __syncthreads();
    }

#pragma unroll
    for (int mt = 0; mt < 4; mt++) {
#pragma unroll
        for (int nt = 0; nt < 4; nt++) {
            const int row = brow + wm + mt * 16 + g;
            const int col = bcol + wn + nt * 8 + 2 * tg;
            float b0 = 0.f, b1 = 0.f;
            if (bias) { b0 = bias[col]; b1 = bias[col + 1]; }
            *(float2*)(C + (long)row * EE + col) =
                make_float2(acc[mt][nt][0] + b0, acc[mt][nt][1] + b1);
            *(float2*)(C + (long)(row + 8) * EE + col) =
                make_float2(acc[mt][nt][2] + b0, acc[mt][nt][3] + b1);
        }
    }
}

// ---------------------------------------------------------------------------
// Tensor-core flash attention (tf32 mma.sync), causal, scale folded into Q.
// Block: 128 q-rows, 8 warps x 16 rows. KV tiles of 64.
// smem: Ks[64][68], Vs[64][72], Ps[8 warps][16][68]; Q staged over Ks+Vs.
// ---------------------------------------------------------------------------
#define KSTR 68
#define VSTR 72
#define NEG_BIG (-1e30f)
#define FLASH_SMEMF (64 * KSTR + 64 * VSTR + 8 * 16 * KSTR)   // 17664 floats

__global__ void __launch_bounds__(256, 2)
flash_tc(const float* __restrict__ Qg, const float* __restrict__ Kg,
         const float* __restrict__ Vg, float* __restrict__ Og)
{
    extern __shared__ float smem[];
    float* Qs = smem;                       // [128][68] staging (overlaps Ks,Vs)
    float* Ks = smem;                       // [64][68]
    float* Vs = smem + 64 * KSTR;           // [64][72]
    float* Ps = smem + 64 * KSTR + 64 * VSTR;

    const uint32_t smb = smem_u32(smem);
    const int tid = threadIdx.x;
    const int w = tid >> 5, lane = tid & 31;
    const int g = lane >> 2, tg = lane & 3;
    const int qt = blockIdx.x;
    const int b = blockIdx.y / HH, h = blockIdx.y % HH;
    const int wm = w * 16;
    const int qlo = qt * 128 + wm;          // warp's first q row

    const float* Qb = Qg + (long)b * SS * EE + h * DD;
    const float* Kb = Kg + (long)b * SS * EE + h * DD;
    const float* Vb = Vg + (long)b * SS * EE + h * DD;
    float*       Ob = Og + (long)b * SS * EE + h * DD;

    // ---- stage Q tile [128][64] -> Qs stride 68, extract fragments ----
    {
        const int r = tid >> 1, c = (tid & 1) * 32;
        const float* src = Qb + (long)(qt * 128 + r) * EE + c;
        const uint32_t dst = smb + (r * KSTR + c) * 4;
#pragma unroll
        for (int j = 0; j < 8; j++) cp_async16(dst + j * 16, src + j * 4);
        CP_COMMIT(); CP_WAIT(0);
    }
    __syncthreads();

    uint32_t qf[8][4];
    const float sc = 0.03125f;   // 1/sqrt(1024), folded into Q
#pragma unroll
    for (int ks = 0; ks < 8; ks++) {
        qf[ks][0] = f2tf32(Qs[(wm + g)     * KSTR + tg     + 8 * ks] * sc);
        qf[ks][1] = f2tf32(Qs[(wm + g + 8) * KSTR + tg     + 8 * ks] * sc);
        qf[ks][2] = f2tf32(Qs[(wm + g)     * KSTR + tg + 4 + 8 * ks] * sc);
        qf[ks][3] = f2tf32(Qs[(wm + g + 8) * KSTR + tg + 4 + 8 * ks] * sc);
    }
    __syncthreads();

    float of[8][4];
#pragma unroll
    for (int i = 0; i < 8; i++)
#pragma unroll
        for (int j = 0; j < 4; j++) of[i][j] = 0.f;
    float m0 = NEG_BIG, m1 = NEG_BIG, l0 = 0.f, l1 = 0.f;
    float* Pw = Ps + w * 16 * KSTR;

    const int ntiles = 2 * qt + 2;
    for (int kt = 0; kt < ntiles; kt++) {
        // ---- load K,V tile via cp.async ----
        {
            const int r = tid >> 2, c = (tid & 3) * 16;
            const float* ksrc = Kb + (long)(kt * 64 + r) * EE + c;
            const float* vsrc = Vb + (long)(kt * 64 + r) * EE + c;
            const uint32_t kdst = smb + (r * KSTR + c) * 4;
            const uint32_t vdst = smb + (64 * KSTR + r * VSTR + c) * 4;
#pragma unroll
            for (int j = 0; j < 4; j++) cp_async16(kdst + j * 16, ksrc + j * 4);
#pragma unroll
            for (int j = 0; j < 4; j++) cp_async16(vdst + j * 16, vsrc + j * 4);
            CP_COMMIT(); CP_WAIT(0);
        }
        __syncthreads();

        if (kt * 64 <= qlo + 15) {   // warp not fully masked
            // ---- S = Q K^T ----
            float s[8][4];
#pragma unroll
            for (int nt = 0; nt < 8; nt++) {
                float c4[4] = {0.f, 0.f, 0.f, 0.f};
#pragma unroll
                for (int ks = 0; ks < 8; ks++) {
                    uint32_t bb[2];
                    bb[0] = f2tf32(Ks[(nt * 8 + g) * KSTR + tg     + 8 * ks]);
                    bb[1] = f2tf32(Ks[(nt * 8 + g) * KSTR + tg + 4 + 8 * ks]);
                    mma_tf32(c4, qf[ks], bb);
                }
                s[nt][0] = c4[0]; s[nt][1] = c4[1]; s[nt][2] = c4[2]; s[nt][3] = c4[3];
            }

            // ---- causal mask (only tiles straddling the diagonal) ----
            if (kt * 64 + 63 > qlo) {
                const int r0g = qlo + g, r1g = qlo + g + 8;
#pragma unroll
                for (int nt = 0; nt < 8; nt++) {
                    const int col = kt * 64 + nt * 8 + 2 * tg;
                    if (col     > r0g) s[nt][0] = NEG_BIG;
                    if (col + 1 > r0g) s[nt][1] = NEG_BIG;
                    if (col     > r1g) s[nt][2] = NEG_BIG;
                    if (col + 1 > r1g) s[nt][3] = NEG_BIG;
                }
            }

            // ---- online softmax (rows g, g+8) ----
            float a0 = NEG_BIG, a1 = NEG_BIG;
#pragma unroll
            for (int nt = 0; nt < 8; nt++) {
                a0 = fmaxf(a0, fmaxf(s[nt][0], s[nt][1]));
                a1 = fmaxf(a1, fmaxf(s[nt][2], s[nt][3]));
            }
            a0 = fmaxf(a0, __shfl_xor_sync(0xffffffffu, a0, 1));
            a0 = fmaxf(a0, __shfl_xor_sync(0xffffffffu, a0, 2));
            a1 = fmaxf(a1, __shfl_xor_sync(0xffffffffu, a1, 1));
            a1 = fmaxf(a1, __shfl_xor_sync(0xffffffffu, a1, 2));

            const float mn0 = fmaxf(m0, a0), mn1 = fmaxf(m1, a1);
            const float cf0 = __expf(m0 - mn0), cf1 = __expf(m1 - mn1);
            m0 = mn0; m1 = mn1;

            float sum0 = 0.f, sum1 = 0.f;
#pragma unroll
            for (int nt = 0; nt < 8; nt++) {
                float p0 = __expf(s[nt][0] - m0);
                float p1 = __expf(s[nt][1] - m0);
                float p2 = __expf(s[nt][2] - m1);
                float p3 = __expf(s[nt][3] - m1);
                sum0 += p0 + p1; sum1 += p2 + p3;
                *(float2*)&Pw[g       * KSTR + nt * 8 + 2 * tg] = make_float2(p0, p1);
                *(float2*)&Pw[(g + 8) * KSTR + nt * 8 + 2 * tg] = make_float2(p2, p3);
            }
            sum0 += __shfl_xor_sync(0xffffffffu, sum0, 1);
            sum0 += __shfl_xor_sync(0xffffffffu, sum0, 2);
            sum1 += __shfl_xor_sync(0xffffffffu, sum1, 1);
            sum1 += __shfl_xor_sync(0xffffffffu, sum1, 2);
            l0 = l0 * cf0 + sum0;
            l1 = l1 * cf1 + sum1;
#pragma unroll
            for (int nt = 0; nt < 8; nt++) {
                of[nt][0] *= cf0; of[nt][1] *= cf0;
                of[nt][2] *= cf1; of[nt][3] *= cf1;
            }
            __syncwarp();

            // ---- O += P V ----
#pragma unroll
            for (int ks = 0; ks < 8; ks++) {
                uint32_t af[4];
                af[0] = f2tf32(Pw[g       * KSTR + tg     + 8 * ks]);
                af[1] = f2tf32(Pw[(g + 8) * KSTR + tg     + 8 * ks]);
                af[2] = f2tf32(Pw[g       * KSTR + tg + 4 + 8 * ks]);
                af[3] = f2tf32(Pw[(g + 8) * KSTR + tg + 4 + 8 * ks]);
#pragma unroll
                for (int dn = 0; dn < 8; dn++) {
                    uint32_t bb[2];
                    bb[0] = f2tf32(Vs[(tg     + 8 * ks) * VSTR + dn * 8 + g]);
                    bb[1] = f2tf32(Vs[(tg + 4 + 8 * ks) * VSTR + dn * 8 + g]);
                    mma_tf32(of[dn], af, bb);
                }
            }
        }
        __syncthreads();   // protect Ks/Vs before next tile
    }

    // ---- epilogue: normalize + store ----
    const float i0 = 1.f / l0, i1 = 1.f / l1;
    const int r0g = qt * 128 + wm + g, r1g = r0g + 8;
#pragma unroll
    for (int dn = 0; dn < 8; dn++) {
        const int col = dn * 8 + 2 * tg;
        *(float2*)(Ob + (long)r0g * EE + col) =
            make_float2(of[dn][0] * i0, of[dn][1] * i0);
        *(float2*)(Ob + (long)r1g * EE + col) =
            make_float2(of[dn][2] * i1, of[dn][3] * i1);
    }
}

// ---------------------------------------------------------------------------
extern "C" void kernel_launch(void* const* d_in, const int* in_sizes, int n_in,
                              void* d_out, int out_size)
{
    const float* x  = (const float*)d_in[0];
    const float* Wq = (const float*)d_in[1];
    const float* Wk = (const float*)d_in[2];
    const float* Wv = (const float*)d_in[3];
    const float* Wo = (const float*)d_in[4];
    const float* bo = (const float*)d_in[5];
    float* out = (float*)d_out;

    float *q, *k, *v, *a;
    cudaGetSymbolAddress((void**)&q, g_q);
    cudaGetSymbolAddress((void**)&k, g_k);
    cudaGetSymbolAddress((void**)&v, g_v);
    cudaGetSymbolAddress((void**)&a, g_attn);

    const int gemm_smem = 4 * TILE_F * sizeof(float);   // 73728 B
    cudaFuncSetAttribute(gemm_tf32,
                         cudaFuncAttributeMaxDynamicSharedMemorySize, gemm_smem);

    dim3 gg(EE / 128, BSROWS / 128);   // (8, 64)
    gemm_tf32<<<gg, 256, gemm_smem>>>(x, Wq, nullptr, q);
    gemm_tf32<<<gg, 256, gemm_smem>>>(x, Wk, nullptr, k);
    gemm_tf32<<<gg, 256, gemm_smem>>>(x, Wv, nullptr, v);

    const int flash_smem = FLASH_SMEMF * sizeof(float);  // 70656 B
    cudaFuncSetAttribute(flash_tc,
                         cudaFuncAttributeMaxDynamicSharedMemorySize, flash_smem);
    flash_tc<<<dim3(SS / 128, BB * HH), 256, flash_smem>>>(q, k, v, a);

    gemm_tf32<<<gg, 256, gemm_smem>>>(a, Wo, bo, out);
}